// round 15
// baseline (speedup 1.0000x reference)
#include <cuda_runtime.h>

#define B_    4096
#define F_    100
#define TPB   128
#define NPAIR 4950

typedef unsigned long long ull;

static __device__ __forceinline__ ull fma2(ull a, ull b, ull c) {
    ull d; asm("fma.rn.f32x2 %0, %1, %2, %3;" : "=l"(d) : "l"(a), "l"(b), "l"(c)); return d;
}
static __device__ __forceinline__ ull mul2(ull a, ull b) {
    ull d; asm("mul.rn.f32x2 %0, %1, %2;" : "=l"(d) : "l"(a), "l"(b)); return d;
}
static __device__ __forceinline__ ull add2(ull a, ull b) {
    ull d; asm("add.rn.f32x2 %0, %1, %2;" : "=l"(d) : "l"(a), "l"(b)); return d;
}
static __device__ __forceinline__ float2 u2f(ull r) {
    float2 v; asm("mov.b64 {%0,%1}, %2;" : "=f"(v.x), "=f"(v.y) : "l"(r)); return v;
}
// dot of 16 floats (8 packed f32x2); two independent chains, add2 merge (R13-correct)
static __device__ __forceinline__ float dot16(const ull* q, const ull* k) {
    ull a = mul2(q[0], k[0]);
    ull b = mul2(q[1], k[1]);
    a = fma2(q[2], k[2], a);
    b = fma2(q[3], k[3], b);
    a = fma2(q[4], k[4], a);
    b = fma2(q[5], k[5], b);
    a = fma2(q[6], k[6], a);
    b = fma2(q[7], k[7], b);
    float2 s = u2f(add2(a, b));
    return s.x + s.y;
}

// X row rotation: full 16-chunk spread for both even and odd rows (3r/2 mod 16)
#define XROT(r) ((r) + ((r) >> 1))

// Fused-kernel shared memory (floats):
//   Xs  [50][64]  chunk c of local row r at 4*((c+XROT(r))&15)  : 0    .. 3200
//                 aliased AFTER projection: part[100][4] at 0..400,
//                                           z0s[100]     at 512..612
//   Wt  [32][64]  slot-major q*scale|k, chunk dc of slot s at
//                 s*64 + 4*((dc+s)&15) + (d&3)                  : 3200 .. 5248
//   wvc [64]      wv column 0 (linear)                          : 5248 .. 5312
//   Qs  [100][20] chunk m of row f at 4*((m+(f>>1))&3)          : 5312 .. 7312
//   Kv  [100][20] same rotation                                 : 7312 .. 9312
//   Vp  [104]                                                   : 9312 .. 9416
//   xc0 [104]     x[:,0] (persists staging -> output)           : 9416 .. 9520
#define SM_W   3200
#define SM_WV  5248
#define SM_Q   5312
#define SM_K   7312
#define SM_V   9312
#define SM_X0  9416
#define SM_TOT 9520   // 38080 B -> 6 CTAs/SM (6*38080 = 228480 <= 233472)

// wq pre-scale: (1/sqrt(HID)) * log2(e), so attention uses exp2 directly.
#define WQ_SCALE 0.36067376022224085f

__global__ void __launch_bounds__(TPB, 6) dcap_fused(
    const float* __restrict__ x,  const float* __restrict__ wq,
    const float* __restrict__ wk, const float* __restrict__ wv,
    float* __restrict__ out)
{
    extern __shared__ float sm[];
    float* Xs  = sm;
    float* Wt  = sm + SM_W;
    float* wvc = sm + SM_WV;
    float* Qs  = sm + SM_Q;
    float* Kv  = sm + SM_K;
    float* Vp  = sm + SM_V;
    float* xc0 = sm + SM_X0;
    float* part= sm;                  // aliases Xs[0..400)   (attention phase)
    float* z0s = sm + 512;            // aliases Xs[512..612) (output phase)

    const int t = threadIdx.x;
    const int b = blockIdx.x;
    const int warp = t >> 5;
    const int lane = t & 31;

    // ---- W: coalesced LDG, swizzled STS (slot-rotated chunks) ----
    #pragma unroll
    for (int it = 0; it < 16; it++) {
        int i = it * TPB + t;
        int m = i >> 10, j = i & 1023;
        int d = j >> 4, s16 = j & 15;
        int slot = (m << 4) | s16;
        float v = m ? wk[d * 64 + s16] : wq[d * 64 + s16] * WQ_SCALE;
        Wt[slot * 64 + ((((d >> 2) + slot) & 15) << 2) + (d & 3)] = v;
    }
    if (t < 64) wvc[t] = wv[t * 64];

    const float4* gx = (const float4*)(x + (size_t)b * (F_ * 64));

    // ---- Two passes of 50 rows: stage X (rotated), project Q/K/v, x0 ----
    #pragma unroll 1
    for (int p = 0; p < 2; p++) {
        const int base = p * 50;
        __syncthreads();                 // Xs reusable; p==0 also publishes Wt
        for (int i = t; i < 50 * 16; i += TPB) {
            int r = i >> 4, c = i & 15;
            *(float4*)(Xs + r * 64 + (((c + XROT(r)) & 15) << 2)) = __ldcs(&gx[(base + r) * 16 + c]);
        }
        __syncthreads();

        if (t < 50) xc0[base + t] = Xs[t * 64 + ((XROT(t) & 15) << 2)];   // x0

        // projection: warp = slot group (broadcast W), lane = local row pair
        if (lane < 25) {
            const int grp = warp;
            const int sbase = grp * 8;
            const float* Wg = Wt + sbase * 64;
            float* dstp = (grp < 2) ? Qs : Kv;
            const int chb = (grp & 1) * 2;
            const int r0 = 2 * lane, r1 = r0 + 1;        // local rows
            const int f0 = base + r0, f1 = f0 + 1;        // global rows
            const int rpg = f0 >> 1;
            const int rot0 = XROT(r0), rot1 = XROT(r1);

            ull a0[8], a1[8];
            #pragma unroll
            for (int k = 0; k < 8; k++) { a0[k] = 0ull; a1[k] = 0ull; }
            #pragma unroll
            for (int d4 = 0; d4 < 16; d4++) {
                ulonglong2 xv0 = *(const ulonglong2*)(Xs + r0 * 64 + (((d4 + rot0) & 15) << 2));
                ulonglong2 xv1 = *(const ulonglong2*)(Xs + r1 * 64 + (((d4 + rot1) & 15) << 2));
                #pragma unroll
                for (int k = 0; k < 8; k++) {
                    // warp-uniform broadcast; rotation indexed by slot (uniform)
                    ulonglong2 w = *(const ulonglong2*)(Wg + k * 64 + (((d4 + sbase + k) & 15) << 2));
                    a0[k] = fma2(xv0.x, w.x, a0[k]);
                    a0[k] = fma2(xv0.y, w.y, a0[k]);
                    a1[k] = fma2(xv1.x, w.x, a1[k]);
                    a1[k] = fma2(xv1.y, w.y, a1[k]);
                }
            }
            float s0[8], s1[8];
            #pragma unroll
            for (int k = 0; k < 8; k++) {
                float2 v0 = u2f(a0[k]); s0[k] = v0.x + v0.y;
                float2 v1 = u2f(a1[k]); s1[k] = v1.x + v1.y;
            }
            #pragma unroll
            for (int cc = 0; cc < 2; cc++) {
                int pos = (((chb + cc) + rpg) & 3) << 2;
                *(float4*)(dstp + f0 * 20 + pos) =
                    make_float4(s0[4 * cc], s0[4 * cc + 1], s0[4 * cc + 2], s0[4 * cc + 3]);
                *(float4*)(dstp + f1 * 20 + pos) =
                    make_float4(s1[4 * cc], s1[4 * cc + 1], s1[4 * cc + 2], s1[4 * cc + 3]);
            }
        }
        // v column (head0/hid0 of x@wv)
        if (t < 50) {
            const ulonglong2* wv2 = (const ulonglong2*)wvc;
            const int rot = XROT(t);
            ull a = 0ull, c = 0ull;
            #pragma unroll
            for (int d4 = 0; d4 < 16; d4++) {
                ulonglong2 xv = *(const ulonglong2*)(Xs + t * 64 + (((d4 + rot) & 15) << 2));
                ulonglong2 w  = wv2[d4];
                a = fma2(xv.x, w.x, a);
                c = fma2(xv.y, w.y, c);
            }
            float2 fs = u2f(add2(a, c));
            Vp[base + t] = fs.x + fs.y;
        }
    }
    __syncthreads();   // all Xs reads done -> part may alias Xs below

    // ---- Attention: 25 items/warp; g warp-uniform -> K loads broadcast.
    //      Scores pre-scaled by log2e -> exp2f; no max-subtract (scores O(1..10)).
    {
        const int half = warp & 1;
        const int pr   = (warp >> 1) * 25 + lane;
        if (lane < 25) {
            const int r0 = 2 * pr;
            ull q[2][8];
            #pragma unroll
            for (int r = 0; r < 2; r++) {
                const int rr = r0 + r, rot = (rr >> 1) & 3;
                #pragma unroll
                for (int m = 0; m < 4; m++) {
                    ulonglong2 v = *(const ulonglong2*)(Qs + rr * 20 + (((m + rot) & 3) << 2));
                    q[r][2 * m] = v.x; q[r][2 * m + 1] = v.y;
                }
            }
            float den0 = 0.f, den1 = 0.f, za0 = 0.f, za1 = 0.f;
            const int gb = half * 50;
            #pragma unroll 2
            for (int gi = 0; gi < 50; gi += 2) {
                const int g = gb + gi;
                const int rot = (g >> 1) & 3;
                ull k0[8], k1[8];
                #pragma unroll
                for (int m = 0; m < 4; m++) {
                    int pos = ((m + rot) & 3) << 2;
                    ulonglong2 va = *(const ulonglong2*)(Kv + g * 20 + pos);
                    ulonglong2 vb = *(const ulonglong2*)(Kv + (g + 1) * 20 + pos);
                    k0[2 * m] = va.x; k0[2 * m + 1] = va.y;
                    k1[2 * m] = vb.x; k1[2 * m + 1] = vb.y;
                }
                float2 vv = *(const float2*)(Vp + g);
                float s00 = dot16(q[0], k0);
                float s01 = dot16(q[0], k1);
                float s10 = dot16(q[1], k0);
                float s11 = dot16(q[1], k1);
                float e00 = exp2f(s00), e01 = exp2f(s01);
                float e10 = exp2f(s10), e11 = exp2f(s11);
                den0 += e00 + e01;
                den1 += e10 + e11;
                za0 = fmaf(e00, vv.x, fmaf(e01, vv.y, za0));
                za1 = fmaf(e10, vv.x, fmaf(e11, vv.y, za1));
            }
            *(float4*)(part + (half * 50 + pr) * 4) = make_float4(den0, za0, den1, za1);
        }
    }
    __syncthreads();
    if (t < 50) {
        float4 p0 = *(const float4*)(part + t * 4);
        float4 p1 = *(const float4*)(part + (50 + t) * 4);
        z0s[2 * t]     = __fdividef(p0.y + p1.y, p0.x + p1.x);
        z0s[2 * t + 1] = __fdividef(p0.w + p1.w, p0.z + p1.z);
    }
    __syncthreads();

    // ---- Output: p[pair(i,j)] = z0[i] * x[j,0]  (R6-form triangular loop) ----
    float* ob = out + (size_t)b * NPAIR;
    const int imax = 99 - t;               // thread t covers (i, j=i+1+t) for i < 99-t
    int rowoff = 0;
    #pragma unroll 1
    for (int i = 0; i < imax; i++) {
        __stcs(ob + rowoff + t, z0s[i] * xc0[i + 1 + t]);
        rowoff += 99 - i;                  // incremental row start
    }
}

extern "C" void kernel_launch(void* const* d_in, const int* in_sizes, int n_in,
                              void* d_out, int out_size)
{
    const float* x  = (const float*)d_in[0];
    const float* wq = (const float*)d_in[1];
    const float* wk = (const float*)d_in[2];
    const float* wv = (const float*)d_in[3];
    float* out = (float*)d_out;
    (void)in_sizes; (void)n_in; (void)out_size;

    const int smem = SM_TOT * (int)sizeof(float);
    cudaFuncSetAttribute(dcap_fused, cudaFuncAttributeMaxDynamicSharedMemorySize, smem);
    dcap_fused<<<B_, TPB, smem>>>(x, wq, wk, wv, out);
}

// round 16
// speedup vs baseline: 1.1289x; 1.1289x over previous
#include <cuda_runtime.h>

#define B_    4096
#define F_    100
#define TPB   128
#define NPAIR 4950

typedef unsigned long long ull;

static __device__ __forceinline__ ull fma2(ull a, ull b, ull c) {
    ull d; asm("fma.rn.f32x2 %0, %1, %2, %3;" : "=l"(d) : "l"(a), "l"(b), "l"(c)); return d;
}
static __device__ __forceinline__ ull mul2(ull a, ull b) {
    ull d; asm("mul.rn.f32x2 %0, %1, %2;" : "=l"(d) : "l"(a), "l"(b)); return d;
}
static __device__ __forceinline__ ull add2(ull a, ull b) {
    ull d; asm("add.rn.f32x2 %0, %1, %2;" : "=l"(d) : "l"(a), "l"(b)); return d;
}
static __device__ __forceinline__ float2 u2f(ull r) {
    float2 v; asm("mov.b64 {%0,%1}, %2;" : "=f"(v.x), "=f"(v.y) : "l"(r)); return v;
}
// dot of 16 floats (8 packed f32x2); two independent chains, add2 merge
static __device__ __forceinline__ float dot16(const ull* q, const ull* k) {
    ull a = mul2(q[0], k[0]);
    ull b = mul2(q[1], k[1]);
    a = fma2(q[2], k[2], a);
    b = fma2(q[3], k[3], b);
    a = fma2(q[4], k[4], a);
    b = fma2(q[5], k[5], b);
    a = fma2(q[6], k[6], a);
    b = fma2(q[7], k[7], b);
    float2 s = u2f(add2(a, b));
    return s.x + s.y;
}

// X row rotation: full 16-chunk spread for both even and odd rows (3r/2 mod 16)
#define XROT(r) ((r) + ((r) >> 1))

// Scratch: per batch 256 floats — z0 at [b*256+f], x0 at [b*256+128+f]. 4 MB, L2-resident.
__device__ float g_z0x0[(size_t)B_ * 256];

// K1 shared memory (floats):
//   Xs  [50][64]  chunk c of local row r at 4*((c+XROT(r))&15)  : 0    .. 3200
//                 (region aliased by part[100][4] during attention)
//   Wt  [32][64]  slot-major q*scale|k, chunk dc of slot s at
//                 s*64 + 4*((dc+s)&15) + (d&3)                  : 3200 .. 5248
//   wvc [64]      wv column 0 (linear)                          : 5248 .. 5312
//   Qs  [100][20] chunk m of row f at 4*((m+(f>>1))&3)          : 5312 .. 7312
//   Kv  [100][20] same rotation                                 : 7312 .. 9312
//   Vp  [104]                                                   : 9312 .. 9416
#define SM_W   3200
#define SM_WV  5248
#define SM_Q   5312
#define SM_K   7312
#define SM_V   9312
#define SM_TOT 9416   // 37664 B -> 6 CTAs/SM

// wq pre-scale: (1/sqrt(HID)) * log2(e), so attention uses exp2 directly.
#define WQ_SCALE 0.36067376022224085f

__global__ void __launch_bounds__(TPB, 6) dcap_k1(
    const float* __restrict__ x,  const float* __restrict__ wq,
    const float* __restrict__ wk, const float* __restrict__ wv)
{
    extern __shared__ float sm[];
    float* Xs  = sm;
    float* Wt  = sm + SM_W;
    float* wvc = sm + SM_WV;
    float* Qs  = sm + SM_Q;
    float* Kv  = sm + SM_K;
    float* Vp  = sm + SM_V;
    float* part= sm;                  // aliases Xs (attention phase only)

    const int t = threadIdx.x;
    const int b = blockIdx.x;
    const int warp = t >> 5;
    const int lane = t & 31;
    float* zx = g_z0x0 + (size_t)b * 256;

    // ---- W staging: float4 LDG (4/thread), swizzled STS ----
    #pragma unroll
    for (int it = 0; it < 4; it++) {
        int i = it * TPB + t;             // 0..511 float4 items
        int m = i >> 8;                   // 0 = q, 1 = k
        int r = i & 255;
        int d = r >> 2, q4 = r & 3;       // row d, quad q4 -> slots q4*4..+3
        const float* src = m ? wk : wq;
        float4 v4 = *(const float4*)(src + d * 64 + q4 * 4);
        if (!m) { v4.x *= WQ_SCALE; v4.y *= WQ_SCALE; v4.z *= WQ_SCALE; v4.w *= WQ_SCALE; }
        float vs[4] = {v4.x, v4.y, v4.z, v4.w};
        #pragma unroll
        for (int e = 0; e < 4; e++) {
            int slot = (m << 4) + q4 * 4 + e;
            Wt[slot * 64 + ((((d >> 2) + slot) & 15) << 2) + (d & 3)] = vs[e];
        }
    }
    if (t < 64) wvc[t] = wv[t * 64];

    const float4* gx = (const float4*)(x + (size_t)b * (F_ * 64));

    // ---- Two passes of 50 rows: stage X (rotated), project Q/K/v, x0 ----
    #pragma unroll 1
    for (int p = 0; p < 2; p++) {
        const int base = p * 50;
        __syncthreads();                 // Xs reusable; p==0 also publishes Wt
        for (int i = t; i < 50 * 16; i += TPB) {
            int r = i >> 4, c = i & 15;
            *(float4*)(Xs + r * 64 + (((c + XROT(r)) & 15) << 2)) = __ldcs(&gx[(base + r) * 16 + c]);
        }
        __syncthreads();

        if (t < 50) zx[128 + base + t] = Xs[t * 64 + ((XROT(t) & 15) << 2)];   // x0

        // projection: warp = slot group (broadcast W), lane = local row pair
        if (lane < 25) {
            const int grp = warp;
            const int sbase = grp * 8;
            const float* Wg = Wt + sbase * 64;
            float* dstp = (grp < 2) ? Qs : Kv;
            const int chb = (grp & 1) * 2;
            const int r0 = 2 * lane, r1 = r0 + 1;        // local rows
            const int f0 = base + r0, f1 = f0 + 1;        // global rows
            const int rpg = f0 >> 1;
            const int rot0 = XROT(r0), rot1 = XROT(r1);

            ull a0[8], a1[8];
            #pragma unroll
            for (int k = 0; k < 8; k++) { a0[k] = 0ull; a1[k] = 0ull; }
            #pragma unroll
            for (int d4 = 0; d4 < 16; d4++) {
                ulonglong2 xv0 = *(const ulonglong2*)(Xs + r0 * 64 + (((d4 + rot0) & 15) << 2));
                ulonglong2 xv1 = *(const ulonglong2*)(Xs + r1 * 64 + (((d4 + rot1) & 15) << 2));
                #pragma unroll
                for (int k = 0; k < 8; k++) {
                    // warp-uniform broadcast; rotation indexed by slot (uniform)
                    ulonglong2 w = *(const ulonglong2*)(Wg + k * 64 + (((d4 + sbase + k) & 15) << 2));
                    a0[k] = fma2(xv0.x, w.x, a0[k]);
                    a0[k] = fma2(xv0.y, w.y, a0[k]);
                    a1[k] = fma2(xv1.x, w.x, a1[k]);
                    a1[k] = fma2(xv1.y, w.y, a1[k]);
                }
            }
            float s0[8], s1[8];
            #pragma unroll
            for (int k = 0; k < 8; k++) {
                float2 v0 = u2f(a0[k]); s0[k] = v0.x + v0.y;
                float2 v1 = u2f(a1[k]); s1[k] = v1.x + v1.y;
            }
            #pragma unroll
            for (int cc = 0; cc < 2; cc++) {
                int pos = (((chb + cc) + rpg) & 3) << 2;
                *(float4*)(dstp + f0 * 20 + pos) =
                    make_float4(s0[4 * cc], s0[4 * cc + 1], s0[4 * cc + 2], s0[4 * cc + 3]);
                *(float4*)(dstp + f1 * 20 + pos) =
                    make_float4(s1[4 * cc], s1[4 * cc + 1], s1[4 * cc + 2], s1[4 * cc + 3]);
            }
        }
        // v column (head0/hid0 of x@wv)
        if (t < 50) {
            const ulonglong2* wv2 = (const ulonglong2*)wvc;
            const int rot = XROT(t);
            ull a = 0ull, c = 0ull;
            #pragma unroll
            for (int d4 = 0; d4 < 16; d4++) {
                ulonglong2 xv = *(const ulonglong2*)(Xs + t * 64 + (((d4 + rot) & 15) << 2));
                ulonglong2 w  = wv2[d4];
                a = fma2(xv.x, w.x, a);
                c = fma2(xv.y, w.y, c);
            }
            float2 fs = u2f(add2(a, c));
            Vp[base + t] = fs.x + fs.y;
        }
    }
    __syncthreads();   // all Xs reads done -> part may alias Xs below

    // ---- Attention: 25 items/warp; g warp-uniform -> K loads broadcast.
    //      Scores pre-scaled by log2e -> exp2f; no max-subtract (scores O(1..10)).
    {
        const int half = warp & 1;
        const int pr   = (warp >> 1) * 25 + lane;
        if (lane < 25) {
            const int r0 = 2 * pr;
            ull q[2][8];
            #pragma unroll
            for (int r = 0; r < 2; r++) {
                const int rr = r0 + r, rot = (rr >> 1) & 3;
                #pragma unroll
                for (int m = 0; m < 4; m++) {
                    ulonglong2 v = *(const ulonglong2*)(Qs + rr * 20 + (((m + rot) & 3) << 2));
                    q[r][2 * m] = v.x; q[r][2 * m + 1] = v.y;
                }
            }
            float den0 = 0.f, den1 = 0.f, za0 = 0.f, za1 = 0.f;
            const int gb = half * 50;
            #pragma unroll 2
            for (int gi = 0; gi < 50; gi += 2) {
                const int g = gb + gi;
                const int rot = (g >> 1) & 3;
                ull k0[8], k1[8];
                #pragma unroll
                for (int m = 0; m < 4; m++) {
                    int pos = ((m + rot) & 3) << 2;
                    ulonglong2 va = *(const ulonglong2*)(Kv + g * 20 + pos);
                    ulonglong2 vb = *(const ulonglong2*)(Kv + (g + 1) * 20 + pos);
                    k0[2 * m] = va.x; k0[2 * m + 1] = va.y;
                    k1[2 * m] = vb.x; k1[2 * m + 1] = vb.y;
                }
                float2 vv = *(const float2*)(Vp + g);
                float s00 = dot16(q[0], k0);
                float s01 = dot16(q[0], k1);
                float s10 = dot16(q[1], k0);
                float s11 = dot16(q[1], k1);
                float e00 = exp2f(s00), e01 = exp2f(s01);
                float e10 = exp2f(s10), e11 = exp2f(s11);
                den0 += e00 + e01;
                den1 += e10 + e11;
                za0 = fmaf(e00, vv.x, fmaf(e01, vv.y, za0));
                za1 = fmaf(e10, vv.x, fmaf(e11, vv.y, za1));
            }
            *(float4*)(part + (half * 50 + pr) * 4) = make_float4(den0, za0, den1, za1);
        }
    }
    __syncthreads();
    if (t < 50) {
        float4 p0 = *(const float4*)(part + t * 4);
        float4 p1 = *(const float4*)(part + (50 + t) * 4);
        zx[2 * t]     = __fdividef(p0.y + p1.y, p0.x + p1.x);
        zx[2 * t + 1] = __fdividef(p0.w + p1.w, p0.z + p1.z);
    }
}

// ---------------- K2: pair expansion, 2 CTAs/batch (even/odd row interleave) ----------------
__global__ void __launch_bounds__(TPB) dcap_k2(float* __restrict__ out)
{
    __shared__ float z0s[100];
    __shared__ float xc0[104];

    const int t = threadIdx.x;
    const int b = blockIdx.x >> 1;          // batch
    const int c = blockIdx.x & 1;           // row parity handled by this CTA
    const float* zx = g_z0x0 + (size_t)b * 256;

    if (t < 100) {
        z0s[t] = zx[t];
        xc0[t] = zx[128 + t];
    }
    __syncthreads();

    // CTA covers rows i = c, c+2, ...; thread t covers column j = i+1+t.
    // Early exit identical to the R6 form; rowstart(i+2)-rowstart(i) = 197-2i.
    float* ob = out + (size_t)b * NPAIR;
    int rowoff = (c == 0) ? 0 : 99;          // rowstart(0), rowstart(1)
    const int imax = 99 - t;                 // active while i < 99-t
    #pragma unroll 1
    for (int i = c; i < imax; i += 2) {
        __stcs(ob + rowoff + t, z0s[i] * xc0[i + 1 + t]);
        rowoff += 197 - 2 * i;
    }
}

extern "C" void kernel_launch(void* const* d_in, const int* in_sizes, int n_in,
                              void* d_out, int out_size)
{
    const float* x  = (const float*)d_in[0];
    const float* wq = (const float*)d_in[1];
    const float* wk = (const float*)d_in[2];
    const float* wv = (const float*)d_in[3];
    float* out = (float*)d_out;
    (void)in_sizes; (void)n_in; (void)out_size;

    const int smem1 = SM_TOT * (int)sizeof(float);
    cudaFuncSetAttribute(dcap_k1, cudaFuncAttributeMaxDynamicSharedMemorySize, smem1);
    dcap_k1<<<B_, TPB, smem1>>>(x, wq, wk, wv);
    dcap_k2<<<B_ * 2, TPB>>>(out);
}